// round 16
// baseline (speedup 1.0000x reference)
#include <cuda_runtime.h>
#include <cuda_bf16.h>
#include <math.h>
#include <stdint.h>

// ---------------------------------------------------------------------------
// TraditionalSpikingModel via INT8 IMMA (mma.sync m16n8k32 s8) — tcgen05
// unavailable (harness emits compute_103 non-'a' PTX).
//
// Spikes are exact ints 0..7 -> stored as s8. Weights double-quantized per
// output row: w = s*q1 + (s/254)*q2, q1,q2 in [-127,127]. int32 accumulation
// is EXACT; fp32 recombination + BN at epilogue. Final layer single-q.
// GEMM: 128x128x64, 16 warps (512 thr), warp tile 32x32, two int32 acc sets
// (q1 steps -> acc1, q2 steps -> acc2), 4-stage cp.async, 1 barrier/K-step.
// Scans: scalar lane/thread, depth-20 prefetch, __ldcs, s8 spike stores.
// ---------------------------------------------------------------------------

#define T_STEPS 500
#define BATCH   64
#define IN_DIM  440
#define IN_PAD  448
#define HID     1024
#define OUT_DIM 1944
#define MROWS   (T_STEPS * BATCH)        // 32000
#define QMAXF   7.0f
#define INV_SQRT_BN 0.9999950000374997f  // 1/sqrt(1 + 1e-5)
#define INV254  0.003937007874015748f    // 1/254
#define CHUNK   20

// ---------------- device scratch (allocation-free rule) --------------------
__device__ int8_t g_actIn[(size_t)MROWS * IN_PAD];
__device__ int8_t g_act0[(size_t)MROWS * HID];
__device__ int8_t g_act1[(size_t)MROWS * HID];
__device__ float  g_ws[(size_t)MROWS * HID];
__device__ int8_t g_w0q[(size_t)HID * 2 * IN_PAD];       // q1|q2 concat
__device__ int8_t g_wsq[(size_t)3 * HID * 2 * HID];
__device__ int8_t g_wfq[(size_t)OUT_DIM * 2 * HID];
__device__ float  g_s0[HID];
__device__ float  g_ss[3 * HID];
__device__ float  g_sf[OUT_DIM];

// ---------------------------- small helpers --------------------------------
__device__ __forceinline__ uint32_t smem_u32(const void* p) {
    uint32_t a;
    asm("{ .reg .u64 t; cvta.to.shared.u64 t, %1; cvt.u32.u64 %0, t; }"
        : "=r"(a) : "l"(p));
    return a;
}

__device__ __forceinline__ void cp_async16(uint32_t dst, const void* src, uint32_t src_bytes) {
    asm volatile("cp.async.cg.shared.global [%0], [%1], 16, %2;"
                 :: "r"(dst), "l"(src), "r"(src_bytes) : "memory");
}
#define CP_COMMIT() asm volatile("cp.async.commit_group;" ::: "memory")
#define CP_WAIT(n)  asm volatile("cp.async.wait_group %0;" :: "n"(n) : "memory")

__device__ __forceinline__ void ldmatrix_x4(uint32_t& r0, uint32_t& r1,
                                            uint32_t& r2, uint32_t& r3,
                                            uint32_t addr) {
    asm volatile("ldmatrix.sync.aligned.m8n8.x4.shared.b16 {%0,%1,%2,%3}, [%4];"
                 : "=r"(r0), "=r"(r1), "=r"(r2), "=r"(r3) : "r"(addr));
}

__device__ __forceinline__ void mma_s8(int32_t* c, const uint32_t* a, const uint32_t* b) {
    asm volatile(
        "mma.sync.aligned.m16n8k32.row.col.s32.s8.s8.s32 "
        "{%0,%1,%2,%3}, {%4,%5,%6,%7}, {%8,%9}, {%0,%1,%2,%3};"
        : "+r"(c[0]), "+r"(c[1]), "+r"(c[2]), "+r"(c[3])
        : "r"(a[0]), "r"(a[1]), "r"(a[2]), "r"(a[3]), "r"(b[0]), "r"(b[1]));
}

// swizzled byte offset inside a 128-row x 64B tile (4x16B chunks per row)
__device__ __forceinline__ uint32_t tile_off(int r, int c4) {
    return (uint32_t)(r * 64 + ((c4 ^ ((r >> 1) & 3)) << 4));
}

// ---------------------------------------------------------------------------
// Per-row double quantization: one block per output row n.
//   s = max|w| / 127 ; q1 = rint(w/s) ; q2 = rint((w - s*q1)*254/s)
// dst row layout: [q1(0..Kp-1) | q2(0..Kp-1)], zero padded K..Kp.
// ---------------------------------------------------------------------------
__global__ void quant_weights_kernel(const float* __restrict__ src,
                                     int8_t* __restrict__ dst,
                                     float* __restrict__ s1out,
                                     int K, int Kp) {
    const int n = blockIdx.x;
    const int tid = threadIdx.x;   // 256
    const float* w = src + (size_t)n * K;

    float m = 0.f;
    for (int k = tid; k < K; k += 256) m = fmaxf(m, fabsf(w[k]));
    __shared__ float red[8];
    #pragma unroll
    for (int o = 16; o > 0; o >>= 1)
        m = fmaxf(m, __shfl_xor_sync(0xffffffffu, m, o));
    if ((tid & 31) == 0) red[tid >> 5] = m;
    __syncthreads();
    m = red[0];
    #pragma unroll
    for (int i = 1; i < 8; ++i) m = fmaxf(m, red[i]);
    m = fmaxf(m, 1e-30f);

    const float s = m / 127.f;
    const float inv_s = 127.f / m;
    int8_t* d1 = dst + (size_t)n * (2 * Kp);
    int8_t* d2 = d1 + Kp;
    for (int k = tid; k < Kp; k += 256) {
        float wv = (k < K) ? w[k] : 0.f;
        float q1 = fminf(fmaxf(rintf(wv * inv_s), -127.f), 127.f);
        float r  = wv - q1 * s;
        float q2 = fminf(fmaxf(rintf(r * 254.f * inv_s), -127.f), 127.f);
        d1[k] = (int8_t)q1;
        d2[k] = (int8_t)q2;
    }
    if (tid == 0) s1out[n] = s;
}

// ---------------------------------------------------------------------------
// Input scan -> s8 spikes, padded to IN_PAD cols. Scalar lane/thread,
// explicit depth-20 prefetch, streaming loads.
// ---------------------------------------------------------------------------
__global__ void input_scan_kernel(const float* __restrict__ xs,
                                  int8_t* __restrict__ spk) {
    const int L = BATCH * IN_PAD;
    int idx = blockIdx.x * blockDim.x + threadIdx.x;
    if (idx >= L) return;
    int b = idx / IN_PAD, i = idx - b * IN_PAD;
    const bool valid = (i < IN_DIM);
    const float* xp = xs + (size_t)b * IN_DIM + i;
    float vmem = 0.f;
    float x[CHUNK];

    for (int t0 = 0; t0 < T_STEPS; t0 += CHUNK) {
        #pragma unroll
        for (int j = 0; j < CHUNK; ++j)
            x[j] = valid ? __ldcs(xp + (size_t)(t0 + j) * (BATCH * IN_DIM)) : 0.f;
        #pragma unroll
        for (int j = 0; j < CHUNK; ++j) {
            vmem += x[j];
            float o = fminf(fmaxf(rintf(vmem), 0.f), QMAXF);
            spk[(size_t)(t0 + j) * L + idx] = (int8_t)o;
            vmem -= o;
        }
    }
}

// ---------------------------------------------------------------------------
// LIF scan: fp32 ws in (streaming), s8 spikes out.
// ---------------------------------------------------------------------------
__global__ void lif_scan_kernel(const float* __restrict__ ws,
                                const float* __restrict__ taus,
                                int8_t* __restrict__ spk) {
    const int L = BATCH * HID;
    int idx = blockIdx.x * blockDim.x + threadIdx.x;
    if (idx >= L) return;
    const float tau = taus[idx & (HID - 1)];
    float syn = 0.f, vmem = 0.f;
    float x[CHUNK];

    for (int t0 = 0; t0 < T_STEPS; t0 += CHUNK) {
        #pragma unroll
        for (int j = 0; j < CHUNK; ++j)
            x[j] = __ldcs(ws + (size_t)(t0 + j) * L + idx);
        #pragma unroll
        for (int j = 0; j < CHUNK; ++j) {
            syn = fmaf(tau, syn, x[j]);
            vmem += syn;
            float o = fminf(fmaxf(rintf(vmem), 0.f), QMAXF);
            spk[(size_t)(t0 + j) * L + idx] = (int8_t)o;
            vmem -= o;
        }
    }
}

// ---------------------------------------------------------------------------
// INT8 IMMA GEMM + fused scale/BN over virtual Kv (q1|q2 concat):
//   d1 = sum a*q1 (exact int32), d2 = sum a*q2
//   C[m,n] = (s1[n]*(d1 + d2/254))*gamma[n]*INV + beta[n]
// A: [M,Kphys] s8 (M mult of 128). B: [N,Bstride] s8.
// CTA 128x128, BK=64, 512 thr (16 warps 4x4, warp tile 32x32).
// 4-stage cp.async pipeline; steps < nhalf -> acc1, else acc2.
// Smem stage: A 8KB @ s*8192, B 8KB @ 32768 + s*8192 (64 KB total).
// ---------------------------------------------------------------------------
__global__ void __launch_bounds__(512, 1)
gemm_imma_kernel(const int8_t* __restrict__ A,
                 const int8_t* __restrict__ B,
                 const float* __restrict__ s1,
                 const float* __restrict__ gamma,
                 const float* __restrict__ beta,
                 float* __restrict__ C,
                 int N, int Nld, int Kphys, int Kv, int Bstride) {
    extern __shared__ __align__(128) char smem[];
    const uint32_t sm0 = smem_u32(smem);

    const int tid  = threadIdx.x;
    const int wid  = tid >> 5;
    const int lane = tid & 31;
    const int wm   = wid & 3;          // m offset = wm*32
    const int wn   = wid >> 2;         // n offset = wn*32
    const int m0   = blockIdx.y * 128;
    const int n0   = blockIdx.x * 128;

    const int nsteps = Kv / 64;
    const int nhalf  = (Kv > Kphys) ? (nsteps >> 1) : nsteps;

    // ---- global->smem: each thread loads one 16B chunk of A and of B ----
    const int r0 = tid >> 2;           // 0..127
    const int c4 = tid & 3;
    const int brow = n0 + r0;
    const uint32_t bsz = (brow < N) ? 16u : 0u;
    const int8_t* Bp = B + (size_t)min(brow, N - 1) * Bstride + c4 * 16;
    const int8_t* Ap = A + (size_t)(m0 + r0) * Kphys + c4 * 16;
    const uint32_t dOf = tile_off(r0, c4);

    #define ISSUE_LOAD(s)                                                        \
    do {                                                                         \
        int k0 = (s) * 64;                                                       \
        int kA = (k0 >= Kphys) ? (k0 - Kphys) : k0;                              \
        uint32_t aB = sm0 + (uint32_t)((s) & 3) * 8192u;                         \
        cp_async16(aB + dOf, Ap + kA, 16u);                                      \
        cp_async16(aB + 32768u + dOf, Bp + k0, bsz);                             \
        CP_COMMIT();                                                             \
    } while (0)

    // ---- ldmatrix per-lane bases (identical lane mapping to bf16 k16) ----
    const int aRow = wm * 32 + (lane & 15);
    const int aKc  = lane >> 4;                    // +16B half
    const int bRow = wn * 32 + (lane & 7) + ((lane >> 4) << 3);
    const int bKc  = (lane >> 3) & 1;

    int32_t acc1[2][4][4], acc2[2][4][4];
    #pragma unroll
    for (int i = 0; i < 2; ++i)
        #pragma unroll
        for (int g = 0; g < 4; ++g)
            #pragma unroll
            for (int q = 0; q < 4; ++q) { acc1[i][g][q] = 0; acc2[i][g][q] = 0; }

    ISSUE_LOAD(0);
    ISSUE_LOAD(1);
    ISSUE_LOAD(2);

    for (int s = 0; s < nsteps; ++s) {
        if (s + 2 < nsteps)      { CP_WAIT(2); }
        else if (s + 1 < nsteps) { CP_WAIT(1); }
        else                     { CP_WAIT(0); }
        __syncthreads();
        if (s + 3 < nsteps) ISSUE_LOAD(s + 3);

        const uint32_t sAb = sm0 + (uint32_t)(s & 3) * 8192u;
        const uint32_t sBb = sAb + 32768u;
        int32_t (*acc)[4][4] = (s < nhalf) ? acc1 : acc2;

        #pragma unroll
        for (int ks = 0; ks < 2; ++ks) {           // two k32 steps per BK=64
            uint32_t a[2][4], b[2][4];
            #pragma unroll
            for (int i = 0; i < 2; ++i) {
                uint32_t ad = sAb + tile_off(aRow + i * 16, ks * 2 + aKc);
                ldmatrix_x4(a[i][0], a[i][1], a[i][2], a[i][3], ad);
            }
            #pragma unroll
            for (int p = 0; p < 2; ++p) {          // each x4 = two n8 groups
                uint32_t bd = sBb + tile_off(bRow + p * 16, ks * 2 + bKc);
                ldmatrix_x4(b[p][0], b[p][1], b[p][2], b[p][3], bd);
            }
            #pragma unroll
            for (int i = 0; i < 2; ++i)
                #pragma unroll
                for (int g = 0; g < 4; ++g)
                    mma_s8(acc[i][g], a[i], &b[g >> 1][(g & 1) * 2]);
        }
    }
    #undef ISSUE_LOAD

    // ---- epilogue: recombine q1/q2, fused BN, float2 stores ----
    const int colBase = n0 + wn * 32 + (lane & 3) * 2;
    const int rowBase = m0 + wm * 32 + (lane >> 2);
    float sc[4][2], bi[4][2];
    #pragma unroll
    for (int g = 0; g < 4; ++g) {
        int col = colBase + g * 8;
        bool v = col < N;                          // N even, col even
        float sa = v ? s1[col]     : 0.f;
        float sb = v ? s1[col + 1] : 0.f;
        sc[g][0] = v ? sa * gamma[col]     * INV_SQRT_BN : 0.f;
        sc[g][1] = v ? sb * gamma[col + 1] * INV_SQRT_BN : 0.f;
        bi[g][0] = v ? beta[col]     : 0.f;
        bi[g][1] = v ? beta[col + 1] : 0.f;
    }

    #pragma unroll
    for (int i = 0; i < 2; ++i) {
        int row0 = rowBase + i * 16;
        int row1 = row0 + 8;
        #pragma unroll
        for (int g = 0; g < 4; ++g) {
            int col = colBase + g * 8;
            if (col < N) {
                float d00 = (float)acc1[i][g][0] + (float)acc2[i][g][0] * INV254;
                float d01 = (float)acc1[i][g][1] + (float)acc2[i][g][1] * INV254;
                float d10 = (float)acc1[i][g][2] + (float)acc2[i][g][2] * INV254;
                float d11 = (float)acc1[i][g][3] + (float)acc2[i][g][3] * INV254;
                float2 v0, v1;
                v0.x = fmaf(d00, sc[g][0], bi[g][0]);
                v0.y = fmaf(d01, sc[g][1], bi[g][1]);
                v1.x = fmaf(d10, sc[g][0], bi[g][0]);
                v1.y = fmaf(d11, sc[g][1], bi[g][1]);
                *(float2*)(C + (size_t)row0 * Nld + col) = v0;
                *(float2*)(C + (size_t)row1 * Nld + col) = v1;
            }
        }
    }
}

// ---------------------------------------------------------------------------
// In-place row-wise log_softmax over OUT_DIM=1944. One block (256 thr) / row.
// ---------------------------------------------------------------------------
__global__ void logsoftmax_kernel(float* __restrict__ out) {
    const int N = OUT_DIM;
    float* row = out + (size_t)blockIdx.x * N;
    const int tid = threadIdx.x;

    float v[8];
    float mx = -1e30f;
    #pragma unroll
    for (int j = 0; j < 8; ++j) {
        int c = tid + j * 256;
        v[j] = (c < N) ? row[c] : -1e30f;
        mx = fmaxf(mx, v[j]);
    }

    __shared__ float red_max[8];
    __shared__ float red_sum[8];
    #pragma unroll
    for (int o = 16; o > 0; o >>= 1)
        mx = fmaxf(mx, __shfl_xor_sync(0xffffffffu, mx, o));
    if ((tid & 31) == 0) red_max[tid >> 5] = mx;
    __syncthreads();
    mx = red_max[0];
    #pragma unroll
    for (int w = 1; w < 8; ++w) mx = fmaxf(mx, red_max[w]);

    float s = 0.f;
    #pragma unroll
    for (int j = 0; j < 8; ++j) s += expf(v[j] - mx);
    #pragma unroll
    for (int o = 16; o > 0; o >>= 1)
        s += __shfl_xor_sync(0xffffffffu, s, o);
    if ((tid & 31) == 0) red_sum[tid >> 5] = s;
    __syncthreads();
    s = 0.f;
    #pragma unroll
    for (int w = 0; w < 8; ++w) s += red_sum[w];

    const float lse = mx + logf(s);
    #pragma unroll
    for (int j = 0; j < 8; ++j) {
        int c = tid + j * 256;
        if (c < N) row[c] = v[j] - lse;
    }
}

// ---------------------------------------------------------------------------
// Launch sequence
// ---------------------------------------------------------------------------
#define GEMM_SMEM 65536

extern "C" void kernel_launch(void* const* d_in, const int* in_sizes, int n_in,
                              void* d_out, int out_size) {
    const float* xs   = (const float*)d_in[0];
    const float* W0   = (const float*)d_in[1];
    const float* Ws   = (const float*)d_in[2];
    const float* taus = (const float*)d_in[3];
    const float* bng  = (const float*)d_in[4];
    const float* bnb  = (const float*)d_in[5];
    const float* Wf   = (const float*)d_in[6];
    const float* fg   = (const float*)d_in[7];
    const float* fb   = (const float*)d_in[8];
    float* out = (float*)d_out;

    int8_t *actIn, *act0, *act1, *w0q, *wsq, *wfq;
    float *wsb, *s0, *ss, *sf;
    cudaGetSymbolAddress((void**)&actIn, g_actIn);
    cudaGetSymbolAddress((void**)&act0,  g_act0);
    cudaGetSymbolAddress((void**)&act1,  g_act1);
    cudaGetSymbolAddress((void**)&wsb,   g_ws);
    cudaGetSymbolAddress((void**)&w0q,   g_w0q);
    cudaGetSymbolAddress((void**)&wsq,   g_wsq);
    cudaGetSymbolAddress((void**)&wfq,   g_wfq);
    cudaGetSymbolAddress((void**)&s0,    g_s0);
    cudaGetSymbolAddress((void**)&ss,    g_ss);
    cudaGetSymbolAddress((void**)&sf,    g_sf);

    cudaFuncSetAttribute(gemm_imma_kernel,
                         cudaFuncAttributeMaxDynamicSharedMemorySize, GEMM_SMEM);

    // weight quantization (per output row)
    quant_weights_kernel<<<HID, 256>>>(W0, w0q, s0, IN_DIM, IN_PAD);
    quant_weights_kernel<<<3 * HID, 256>>>(Ws, wsq, ss, HID, HID);
    quant_weights_kernel<<<OUT_DIM, 256>>>(Wf, wfq, sf, HID, HID);

    // input spike quantization scan
    input_scan_kernel<<<(BATCH * IN_PAD + 255) / 256, 256>>>(xs, actIn);

    const dim3 grid_h(HID / 128, MROWS / 128);   // 8 x 250

    // layer 0 (Kphys = 448 padded, Kv = 896 q1|q2)
    gemm_imma_kernel<<<grid_h, 512, GEMM_SMEM>>>(
        actIn, w0q, s0, bng, bnb, wsb, HID, HID, IN_PAD, 2 * IN_PAD, 2 * IN_PAD);
    lif_scan_kernel<<<(BATCH * HID) / 256, 256>>>(wsb, taus, act0);

    // layers 1..3 (ping-pong), Kv = 2048 q1|q2
    int8_t* src = act0;
    int8_t* dst = act1;
    for (int l = 1; l < 4; ++l) {
        gemm_imma_kernel<<<grid_h, 512, GEMM_SMEM>>>(
            src, wsq + (size_t)(l - 1) * HID * 2 * HID, ss + (l - 1) * HID,
            bng + l * HID, bnb + l * HID, wsb, HID, HID, HID, 2 * HID, 2 * HID);
        lif_scan_kernel<<<(BATCH * HID) / 256, 256>>>(wsb, taus + l * HID, dst);
        int8_t* tmp = src; src = dst; dst = tmp;
    }

    // final GEMM (single-q: Kv = Kphys = 1024) + BN + softmax, 2 M-chunks
    const int HALF = MROWS / 2;
    for (int c = 0; c < 2; ++c) {
        const int8_t* aC = src + (size_t)c * HALF * HID;
        float* oC = out + (size_t)c * HALF * OUT_DIM;
        gemm_imma_kernel<<<dim3((OUT_DIM + 127) / 128, HALF / 128), 512, GEMM_SMEM>>>(
            aC, wfq, sf, fg, fb, oC, OUT_DIM, OUT_DIM, HID, HID, 2 * HID);
        logsoftmax_kernel<<<HALF, 256>>>(oC);
    }
}

// round 17
// speedup vs baseline: 2.3454x; 2.3454x over previous
#include <cuda_runtime.h>
#include <cuda_bf16.h>
#include <math.h>
#include <stdint.h>

// ---------------------------------------------------------------------------
// TraditionalSpikingModel via HMMA (mma.sync bf16). R17: revert IMMA (R16
// regression); GEMM re-tiled 256x128 CTA / 64x64 warp tiles to relieve the
// shared-memory bandwidth bound (ldsm duplication 48KB -> 32KB per step).
// Hidden layers: w = hi(bf16)+lo(bf16), one GEMM with virtual K'=2K (A wraps).
// Final layer hi-only. Scans: scalar lane, depth-20 prefetch, 64-thr blocks.
// ---------------------------------------------------------------------------

#define T_STEPS 500
#define BATCH   64
#define IN_DIM  440
#define IN_PAD  448
#define HID     1024
#define OUT_DIM 1944
#define MROWS   (T_STEPS * BATCH)        // 32000
#define QMAXF   7.0f
#define INV_SQRT_BN 0.9999950000374997f  // 1/sqrt(1 + 1e-5)
#define CHUNK   20

// ---------------- device scratch (allocation-free rule) --------------------
__device__ __nv_bfloat16 g_actIn[(size_t)MROWS * IN_PAD];
__device__ __nv_bfloat16 g_act0[(size_t)MROWS * HID];
__device__ __nv_bfloat16 g_act1[(size_t)MROWS * HID];
__device__ float         g_ws[(size_t)MROWS * HID];
__device__ __nv_bfloat16 g_w0cat[(size_t)HID * 2 * IN_PAD];
__device__ __nv_bfloat16 g_wscat[(size_t)3 * HID * 2 * HID];
__device__ __nv_bfloat16 g_wf[(size_t)OUT_DIM * HID];

// ---------------------------- small helpers --------------------------------
__device__ __forceinline__ uint32_t smem_u32(const void* p) {
    uint32_t a;
    asm("{ .reg .u64 t; cvta.to.shared.u64 t, %1; cvt.u32.u64 %0, t; }"
        : "=r"(a) : "l"(p));
    return a;
}

__device__ __forceinline__ void cp_async16(uint32_t dst, const void* src, uint32_t src_bytes) {
    asm volatile("cp.async.cg.shared.global [%0], [%1], 16, %2;"
                 :: "r"(dst), "l"(src), "r"(src_bytes) : "memory");
}
#define CP_COMMIT() asm volatile("cp.async.commit_group;" ::: "memory")
#define CP_WAIT(n)  asm volatile("cp.async.wait_group %0;" :: "n"(n) : "memory")

__device__ __forceinline__ void ldmatrix_x4(uint32_t& r0, uint32_t& r1,
                                            uint32_t& r2, uint32_t& r3,
                                            uint32_t addr) {
    asm volatile("ldmatrix.sync.aligned.m8n8.x4.shared.b16 {%0,%1,%2,%3}, [%4];"
                 : "=r"(r0), "=r"(r1), "=r"(r2), "=r"(r3) : "r"(addr));
}

__device__ __forceinline__ void mma_bf16(float* c, const uint32_t* a, const uint32_t* b) {
    asm volatile(
        "mma.sync.aligned.m16n8k16.row.col.f32.bf16.bf16.f32 "
        "{%0,%1,%2,%3}, {%4,%5,%6,%7}, {%8,%9}, {%0,%1,%2,%3};"
        : "+f"(c[0]), "+f"(c[1]), "+f"(c[2]), "+f"(c[3])
        : "r"(a[0]), "r"(a[1]), "r"(a[2]), "r"(a[3]), "r"(b[0]), "r"(b[1]));
}

// swizzled byte offset inside an Nrows x 32 bf16 tile (row = 64B, 4x16B chunks)
__device__ __forceinline__ uint32_t tile_off(int r, int c4) {
    return (uint32_t)(r * 64 + ((c4 ^ ((r >> 1) & 3)) << 4));
}

// ---------------------------------------------------------------------------
// Weight split: dst[n][k] = bf16_hi(w), dst[n][Kp + k] = bf16(w - hi)
// ---------------------------------------------------------------------------
__global__ void split_weights_kernel(const float* __restrict__ src,
                                     __nv_bfloat16* __restrict__ dst,
                                     int N, int K, int Kp) {
    int idx = blockIdx.x * blockDim.x + threadIdx.x;
    if (idx >= N * Kp) return;
    int n = idx / Kp, k = idx - n * Kp;
    float w = (k < K) ? src[(size_t)n * K + k] : 0.f;
    __nv_bfloat16 hi = __float2bfloat16(w);
    float lo = w - __bfloat162float(hi);
    dst[(size_t)n * (2 * Kp) + k]      = hi;
    dst[(size_t)n * (2 * Kp) + Kp + k] = __float2bfloat16(lo);
}

// plain fp32 -> bf16 convert (final-layer weights, hi only)
__global__ void convert_weights_kernel(const float* __restrict__ src,
                                       __nv_bfloat16* __restrict__ dst, int n) {
    int idx = blockIdx.x * blockDim.x + threadIdx.x;
    if (idx < n) dst[idx] = __float2bfloat16(src[idx]);
}

// ---------------------------------------------------------------------------
// Input scan -> bf16 spikes, padded to IN_PAD cols. Scalar lane/thread,
// explicit depth-20 prefetch, streaming loads. 64-thread blocks (balance).
// ---------------------------------------------------------------------------
__global__ void input_scan_kernel(const float* __restrict__ xs,
                                  __nv_bfloat16* __restrict__ spk) {
    const int L = BATCH * IN_PAD;
    int idx = blockIdx.x * blockDim.x + threadIdx.x;
    if (idx >= L) return;
    int b = idx / IN_PAD, i = idx - b * IN_PAD;
    const bool valid = (i < IN_DIM);
    const float* xp = xs + (size_t)b * IN_DIM + i;
    float vmem = 0.f;
    float x[CHUNK];

    for (int t0 = 0; t0 < T_STEPS; t0 += CHUNK) {
        #pragma unroll
        for (int j = 0; j < CHUNK; ++j)
            x[j] = valid ? __ldcs(xp + (size_t)(t0 + j) * (BATCH * IN_DIM)) : 0.f;
        #pragma unroll
        for (int j = 0; j < CHUNK; ++j) {
            vmem += x[j];
            float o = fminf(fmaxf(rintf(vmem), 0.f), QMAXF);
            spk[(size_t)(t0 + j) * L + idx] = __float2bfloat16(o);
            vmem -= o;
        }
    }
}

// ---------------------------------------------------------------------------
// LIF scan: fp32 ws in (streaming), bf16 spikes out. 64-thread blocks.
// ---------------------------------------------------------------------------
__global__ void lif_scan_kernel(const float* __restrict__ ws,
                                const float* __restrict__ taus,
                                __nv_bfloat16* __restrict__ spk) {
    const int L = BATCH * HID;
    int idx = blockIdx.x * blockDim.x + threadIdx.x;
    if (idx >= L) return;
    const float tau = taus[idx & (HID - 1)];
    float syn = 0.f, vmem = 0.f;
    float x[CHUNK];

    for (int t0 = 0; t0 < T_STEPS; t0 += CHUNK) {
        #pragma unroll
        for (int j = 0; j < CHUNK; ++j)
            x[j] = __ldcs(ws + (size_t)(t0 + j) * L + idx);
        #pragma unroll
        for (int j = 0; j < CHUNK; ++j) {
            syn = fmaf(tau, syn, x[j]);
            vmem += syn;
            float o = fminf(fmaxf(rintf(vmem), 0.f), QMAXF);
            spk[(size_t)(t0 + j) * L + idx] = __float2bfloat16(o);
            vmem -= o;
        }
    }
}

// ---------------------------------------------------------------------------
// HMMA GEMM + fused BN over virtual Kv (hi|lo concat or plain):
//   C[m,n] = (sum_k A[m, k % Kphys] * B[n, k]) * gamma[n]*INV + beta[n]
// CTA tile 256x128, BK=32, 256 thr (8 warps 4x2, warp tile 64x64).
// 4-stage cp.async, one barrier per K-step. smem: A 4x16KB + B 4x8KB = 96KB.
// b-fragments software-pipelined inside each k16 step.
// ---------------------------------------------------------------------------
__global__ void __launch_bounds__(256, 1)
gemm_hmma_kernel(const __nv_bfloat16* __restrict__ A,
                 const __nv_bfloat16* __restrict__ B,
                 const float* __restrict__ gamma,
                 const float* __restrict__ beta,
                 float* __restrict__ C,
                 int N, int Nld, int Kphys, int Kv, int Bstride) {
    extern __shared__ __align__(128) char smem[];
    const uint32_t sm0 = smem_u32(smem);    // A: 0..64KB (4x16KB), B: 64..96KB

    const int tid  = threadIdx.x;
    const int wid  = tid >> 5;
    const int lane = tid & 31;
    const int wm   = wid & 3;               // m offset = wm*64
    const int wn   = wid >> 2;              // n offset = wn*64
    const int m0   = blockIdx.y * 256;
    const int n0   = blockIdx.x * 128;

    const int nsteps = Kv / 32;

    // ---- global->smem: A 4 chunks/thread (rows r0+{0,64,128,192}), B 2 ----
    const int r0 = tid >> 2;                // 0..63
    const int c4 = tid & 3;

    const int brow0 = n0 + r0, brow1 = n0 + r0 + 64;
    const uint32_t bsz0 = (brow0 < N) ? 16u : 0u;
    const uint32_t bsz1 = (brow1 < N) ? 16u : 0u;
    const __nv_bfloat16* Bp0 = B + (size_t)min(brow0, N - 1) * Bstride + c4 * 8;
    const __nv_bfloat16* Bp1 = B + (size_t)min(brow1, N - 1) * Bstride + c4 * 8;
    const __nv_bfloat16* Ap = A + (size_t)(m0 + r0) * Kphys + c4 * 8;
    const size_t aRowStride64 = (size_t)64 * Kphys;
    const uint32_t dB0 = tile_off(r0, c4), dB1 = tile_off(r0 + 64, c4);

    #define ISSUE_LOAD(s)                                                        \
    do {                                                                         \
        int k0 = (s) * 32;                                                       \
        int kA = (k0 >= Kphys) ? (k0 - Kphys) : k0;                              \
        uint32_t aB = sm0 + (uint32_t)((s) & 3) * 16384u;                        \
        uint32_t bB = sm0 + 65536u + (uint32_t)((s) & 3) * 8192u;                \
        cp_async16(aB + tile_off(r0,       c4), Ap + kA,                   16u); \
        cp_async16(aB + tile_off(r0 + 64,  c4), Ap + kA + aRowStride64,    16u); \
        cp_async16(aB + tile_off(r0 + 128, c4), Ap + kA + 2*aRowStride64,  16u); \
        cp_async16(aB + tile_off(r0 + 192, c4), Ap + kA + 3*aRowStride64,  16u); \
        cp_async16(bB + dB0, Bp0 + k0, bsz0);                                    \
        cp_async16(bB + dB1, Bp1 + k0, bsz1);                                    \
        CP_COMMIT();                                                             \
    } while (0)

    // ---- ldmatrix per-lane bases ----
    const int aRow = wm * 64 + (lane & 15);
    const int aKc  = lane >> 4;
    const int bRow = wn * 64 + (lane & 7) + ((lane >> 4) << 3);
    const int bKc  = (lane >> 3) & 1;

    float acc[4][8][4];
    #pragma unroll
    for (int i = 0; i < 4; ++i)
        #pragma unroll
        for (int j = 0; j < 8; ++j)
            #pragma unroll
            for (int q = 0; q < 4; ++q) acc[i][j][q] = 0.f;

    ISSUE_LOAD(0);
    ISSUE_LOAD(1);
    ISSUE_LOAD(2);

    for (int s = 0; s < nsteps; ++s) {
        if (s + 2 < nsteps)      { CP_WAIT(2); }
        else if (s + 1 < nsteps) { CP_WAIT(1); }
        else                     { CP_WAIT(0); }
        __syncthreads();
        if (s + 3 < nsteps) ISSUE_LOAD(s + 3);

        const uint32_t sAb = sm0 + (uint32_t)(s & 3) * 16384u;
        const uint32_t sBb = sm0 + 65536u + (uint32_t)(s & 3) * 8192u;

        #pragma unroll
        for (int ks = 0; ks < 2; ++ks) {
            uint32_t a[4][4];
            #pragma unroll
            for (int i = 0; i < 4; ++i) {
                uint32_t ad = sAb + tile_off(aRow + i * 16, ks * 2 + aKc);
                ldmatrix_x4(a[i][0], a[i][1], a[i][2], a[i][3], ad);
            }
            uint32_t b[2][4];
            {
                uint32_t bd = sBb + tile_off(bRow, ks * 2 + bKc);
                ldmatrix_x4(b[0][0], b[0][1], b[0][2], b[0][3], bd);
            }
            #pragma unroll
            for (int p = 0; p < 4; ++p) {
                if (p < 3) {
                    uint32_t bd = sBb + tile_off(bRow + (p + 1) * 16, ks * 2 + bKc);
                    ldmatrix_x4(b[(p + 1) & 1][0], b[(p + 1) & 1][1],
                                b[(p + 1) & 1][2], b[(p + 1) & 1][3], bd);
                }
                #pragma unroll
                for (int i = 0; i < 4; ++i) {
                    mma_bf16(acc[i][2 * p],     a[i], &b[p & 1][0]);
                    mma_bf16(acc[i][2 * p + 1], a[i], &b[p & 1][2]);
                }
            }
        }
    }
    #undef ISSUE_LOAD

    // ---- epilogue: fused BN, float2 stores ----
    const int colBase = n0 + wn * 64 + (lane & 3) * 2;
    float sc[8][2], bi[8][2];
    #pragma unroll
    for (int j = 0; j < 8; ++j) {
        int col = colBase + j * 8;
        bool v = col < N;                    // N even, col even
        sc[j][0] = v ? gamma[col] * INV_SQRT_BN : 0.f;
        sc[j][1] = v ? gamma[col + 1] * INV_SQRT_BN : 0.f;
        bi[j][0] = v ? beta[col] : 0.f;
        bi[j][1] = v ? beta[col + 1] : 0.f;
    }

    const int rowBase = m0 + wm * 64 + (lane >> 2);
    #pragma unroll
    for (int i = 0; i < 4; ++i) {
        int row0 = rowBase + i * 16;
        int row1 = row0 + 8;
        #pragma unroll
        for (int j = 0; j < 8; ++j) {
            int col = colBase + j * 8;
            if (col < N) {
                float2 v0, v1;
                v0.x = fmaf(acc[i][j][0], sc[j][0], bi[j][0]);
                v0.y = fmaf(acc[i][j][1], sc[j][1], bi[j][1]);
                v1.x = fmaf(acc[i][j][2], sc[j][0], bi[j][0]);
                v1.y = fmaf(acc[i][j][3], sc[j][1], bi[j][1]);
                *(float2*)(C + (size_t)row0 * Nld + col) = v0;
                *(float2*)(C + (size_t)row1 * Nld + col) = v1;
            }
        }
    }
}

// ---------------------------------------------------------------------------
// In-place row-wise log_softmax over OUT_DIM=1944. One block (256 thr) / row.
// ---------------------------------------------------------------------------
__global__ void logsoftmax_kernel(float* __restrict__ out) {
    const int N = OUT_DIM;
    float* row = out + (size_t)blockIdx.x * N;
    const int tid = threadIdx.x;

    float v[8];
    float mx = -1e30f;
    #pragma unroll
    for (int j = 0; j < 8; ++j) {
        int c = tid + j * 256;
        v[j] = (c < N) ? row[c] : -1e30f;
        mx = fmaxf(mx, v[j]);
    }

    __shared__ float red_max[8];
    __shared__ float red_sum[8];
    #pragma unroll
    for (int o = 16; o > 0; o >>= 1)
        mx = fmaxf(mx, __shfl_xor_sync(0xffffffffu, mx, o));
    if ((tid & 31) == 0) red_max[tid >> 5] = mx;
    __syncthreads();
    mx = red_max[0];
    #pragma unroll
    for (int w = 1; w < 8; ++w) mx = fmaxf(mx, red_max[w]);

    float s = 0.f;
    #pragma unroll
    for (int j = 0; j < 8; ++j) s += expf(v[j] - mx);
    #pragma unroll
    for (int o = 16; o > 0; o >>= 1)
        s += __shfl_xor_sync(0xffffffffu, s, o);
    if ((tid & 31) == 0) red_sum[tid >> 5] = s;
    __syncthreads();
    s = 0.f;
    #pragma unroll
    for (int w = 0; w < 8; ++w) s += red_sum[w];

    const float lse = mx + logf(s);
    #pragma unroll
    for (int j = 0; j < 8; ++j) {
        int c = tid + j * 256;
        if (c < N) row[c] = v[j] - lse;
    }
}

// ---------------------------------------------------------------------------
// Launch sequence
// ---------------------------------------------------------------------------
#define GEMM_SMEM 98304

extern "C" void kernel_launch(void* const* d_in, const int* in_sizes, int n_in,
                              void* d_out, int out_size) {
    const float* xs   = (const float*)d_in[0];
    const float* W0   = (const float*)d_in[1];
    const float* Ws   = (const float*)d_in[2];
    const float* taus = (const float*)d_in[3];
    const float* bng  = (const float*)d_in[4];
    const float* bnb  = (const float*)d_in[5];
    const float* Wf   = (const float*)d_in[6];
    const float* fg   = (const float*)d_in[7];
    const float* fb   = (const float*)d_in[8];
    float* out = (float*)d_out;

    __nv_bfloat16 *actIn, *act0, *act1, *w0cat, *wscat, *wf;
    float* wsb;
    cudaGetSymbolAddress((void**)&actIn, g_actIn);
    cudaGetSymbolAddress((void**)&act0,  g_act0);
    cudaGetSymbolAddress((void**)&act1,  g_act1);
    cudaGetSymbolAddress((void**)&wsb,   g_ws);
    cudaGetSymbolAddress((void**)&w0cat, g_w0cat);
    cudaGetSymbolAddress((void**)&wscat, g_wscat);
    cudaGetSymbolAddress((void**)&wf,    g_wf);

    cudaFuncSetAttribute(gemm_hmma_kernel,
                         cudaFuncAttributeMaxDynamicSharedMemorySize, GEMM_SMEM);

    // weight preparation
    split_weights_kernel<<<(HID * IN_PAD + 255) / 256, 256>>>(
        W0, w0cat, HID, IN_DIM, IN_PAD);
    split_weights_kernel<<<(3 * HID * HID + 255) / 256, 256>>>(
        Ws, wscat, 3 * HID, HID, HID);
    convert_weights_kernel<<<(OUT_DIM * HID + 255) / 256, 256>>>(
        Wf, wf, OUT_DIM * HID);

    // input spike quantization scan
    input_scan_kernel<<<(BATCH * IN_PAD + 63) / 64, 64>>>(xs, actIn);

    const dim3 grid_h(HID / 128, MROWS / 256);   // 8 x 125

    // layer 0 (Kphys = 448 padded, Kv = 896 hi|lo)
    gemm_hmma_kernel<<<grid_h, 256, GEMM_SMEM>>>(
        actIn, w0cat, bng, bnb, wsb, HID, HID, IN_PAD, 2 * IN_PAD, 2 * IN_PAD);
    lif_scan_kernel<<<(BATCH * HID) / 64, 64>>>(wsb, taus, act0);

    // layers 1..3 (ping-pong), Kv = 2048 hi|lo
    __nv_bfloat16* src = act0;
    __nv_bfloat16* dst = act1;
    for (int l = 1; l < 4; ++l) {
        gemm_hmma_kernel<<<grid_h, 256, GEMM_SMEM>>>(
            src, wscat + (size_t)(l - 1) * HID * 2 * HID,
            bng + l * HID, bnb + l * HID, wsb, HID, HID, HID, 2 * HID, 2 * HID);
        lif_scan_kernel<<<(BATCH * HID) / 64, 64>>>(wsb, taus + l * HID, dst);
        __nv_bfloat16* tmp = src; src = dst; dst = tmp;
    }

    // final GEMM (hi-only, Kv = 1024) + BN into d_out, then log_softmax
    gemm_hmma_kernel<<<dim3((OUT_DIM + 127) / 128, MROWS / 256), 256, GEMM_SMEM>>>(
        src, wf, fg, fb, out, OUT_DIM, OUT_DIM, HID, HID, HID);
    logsoftmax_kernel<<<MROWS, 256>>>(out);
}